// round 4
// baseline (speedup 1.0000x reference)
#include <cuda_runtime.h>
#include <math.h>
#include <stdint.h>

// Problem constants (fixed by the reference: B=8, T=4096, D=1024)
constexpr int Bb   = 8;
constexpr int Tt   = 4096;
constexpr int Dd   = 1024;
constexpr int Mtot = Bb * Tt;          // 32768 rows
constexpr int NC   = 32;               // scan chunks
constexpr int CL   = Tt / NC;          // 128 steps per chunk

// Scratch (device globals — no allocations allowed in kernel_launch)
__device__ float sc_u[(size_t)Mtot * Dd];
__device__ float sc_g[(size_t)Mtot * Dd];
__device__ float sc_h[(size_t)Mtot * Dd];
__device__ float sc_P[Bb * NC * Dd];
__device__ float sc_S[Bb * NC * Dd];
__device__ float sc_C[Bb * NC * Dd];

// ===========================================================================
// tf32 mma.sync GEMM:  C[m,n] = sum_k A[m,k]*W[n,k] + bias[n]  (+sigmoid)
// CTA tile 256x128, BK=16. 8 warps in 4(M)x2(N), each warp 64x64 =
// 4x8 grid of m16n8k8 -> 128 acc regs. Halves LDS/cvt per MMA vs R3.
// cp.async 2-stage double buffer in dynamic SMEM (60KB), pad stride 20
// (conflict-free fragment LDS).
// ===========================================================================
constexpr int BM = 256, BN = 128, BK = 16;
constexpr int NCHUNK = Dd / BK;        // 64
constexpr int LDP    = BK + 4;         // padded row stride (floats)
constexpr int A_STG  = BM * LDP;       // floats per A stage
constexpr int B_STG  = BN * LDP;       // floats per B stage
constexpr int SMEM_BYTES = (2 * A_STG + 2 * B_STG) * 4;   // 61440

__device__ __forceinline__ uint32_t smem_u32(const void* p) {
    uint32_t a;
    asm("{ .reg .u64 t; cvta.to.shared.u64 t, %1; cvt.u32.u64 %0, t; }"
        : "=r"(a) : "l"(p));
    return a;
}
__device__ __forceinline__ void cp16(uint32_t s, const void* g) {
    asm volatile("cp.async.cg.shared.global [%0], [%1], 16;" :: "r"(s), "l"(g));
}
__device__ __forceinline__ uint32_t f2tf(float x) {
    uint32_t r;
    asm("cvt.rna.tf32.f32 %0, %1;" : "=r"(r) : "f"(x));
    return r;
}
__device__ __forceinline__ void mma8(float* d, const uint32_t* a, const uint32_t* b) {
    asm volatile(
        "mma.sync.aligned.m16n8k8.row.col.f32.tf32.tf32.f32 "
        "{%0,%1,%2,%3}, {%4,%5,%6,%7}, {%8,%9}, {%0,%1,%2,%3};"
        : "+f"(d[0]), "+f"(d[1]), "+f"(d[2]), "+f"(d[3])
        : "r"(a[0]), "r"(a[1]), "r"(a[2]), "r"(a[3]), "r"(b[0]), "r"(b[1]));
}

__global__ __launch_bounds__(256, 1)
void gemm_tc(const float* __restrict__ A, const float* __restrict__ W,
             const float* __restrict__ bias, float* __restrict__ C, int act)
{
    extern __shared__ float dynsm[];
    float* As = dynsm;                 // [2][BM][LDP]
    float* Bs = dynsm + 2 * A_STG;     // [2][BN][LDP]

    const int tid  = threadIdx.x;
    const int wid  = tid >> 5;
    const int lane = tid & 31;
    const int lr   = lane >> 2;          // 0..7
    const int lc   = lane & 3;           // 0..3
    const int bnb  = blockIdx.x;         // N tile (0..7)
    const int bmb  = blockIdx.y;         // M tile (0..127)

    const int wm = (wid >> 1) * 64;      // warp M offset (0,64,128,192)
    const int wn = (wid & 1) * 64;       // warp N offset (0,64)

    // ---- loader mapping ----
    // A: one row per thread (256 rows), 4 cp.async x 16B. Conflict-free STS.
    // B: 512 float4 over 2 passes: idx = tid + 256*p, row = idx>>2, quad = idx&3.
    const float4* A4 = reinterpret_cast<const float4*>(A) + ((size_t)bmb * BM) * (Dd / 4);
    const float4* B4 = reinterpret_cast<const float4*>(W) + ((size_t)bnb * BN) * (Dd / 4);

    const int br0 = tid >> 2, bq = tid & 3;   // B pass0 row/quad
    const int br1 = br0 + 64;                 // B pass1 row

    uint32_t sA[2], sB0[2], sB1[2];
    {
        const uint32_t ab = smem_u32(As);
        const uint32_t bb = smem_u32(Bs);
        #pragma unroll
        for (int s = 0; s < 2; s++) {
            sA[s]  = ab + (uint32_t)((s * BM + tid) * LDP) * 4u;
            sB0[s] = bb + (uint32_t)((s * BN + br0) * LDP + bq * 4) * 4u;
            sB1[s] = bb + (uint32_t)((s * BN + br1) * LDP + bq * 4) * 4u;
        }
    }

    #define LOAD_STAGE(c, s) do {                                            \
        const float4* ga = A4 + (size_t)tid * (Dd / 4) + (c) * 4;             \
        cp16(sA[s] + 0,  ga + 0);                                             \
        cp16(sA[s] + 16, ga + 1);                                             \
        cp16(sA[s] + 32, ga + 2);                                             \
        cp16(sA[s] + 48, ga + 3);                                             \
        cp16(sB0[s], B4 + (size_t)br0 * (Dd / 4) + (c) * 4 + bq);             \
        cp16(sB1[s], B4 + (size_t)br1 * (Dd / 4) + (c) * 4 + bq);             \
        asm volatile("cp.async.commit_group;");                               \
    } while (0)

    float acc[4][8][4] = {};

    LOAD_STAGE(0, 0);
    LOAD_STAGE(1, 1);

    for (int c = 0; c < NCHUNK; c++) {
        const int s = c & 1;
        if (c + 1 < NCHUNK) asm volatile("cp.async.wait_group 1;" ::: "memory");
        else                asm volatile("cp.async.wait_group 0;" ::: "memory");
        __syncthreads();

        const float* Ab = As + s * A_STG;
        const float* Bb2 = Bs + s * B_STG;

        #pragma unroll
        for (int ks = 0; ks < 2; ks++) {
            const int k0 = ks * 8;
            uint32_t af[4][4], bf[8][2];
            #pragma unroll
            for (int mi = 0; mi < 4; mi++) {
                const int rr = wm + mi * 16 + lr;
                af[mi][0] = f2tf(Ab[rr * LDP + k0 + lc]);
                af[mi][1] = f2tf(Ab[(rr + 8) * LDP + k0 + lc]);
                af[mi][2] = f2tf(Ab[rr * LDP + k0 + lc + 4]);
                af[mi][3] = f2tf(Ab[(rr + 8) * LDP + k0 + lc + 4]);
            }
            #pragma unroll
            for (int ni = 0; ni < 8; ni++) {
                const int nr = wn + ni * 8 + lr;
                bf[ni][0] = f2tf(Bb2[nr * LDP + k0 + lc]);
                bf[ni][1] = f2tf(Bb2[nr * LDP + k0 + lc + 4]);
            }
            #pragma unroll
            for (int mi = 0; mi < 4; mi++)
                #pragma unroll
                for (int ni = 0; ni < 8; ni++)
                    mma8(acc[mi][ni], af[mi], bf[ni]);
        }

        __syncthreads();
        if (c + 2 < NCHUNK) LOAD_STAGE(c + 2, s);
    }

    // ---- epilogue: bias (+sigmoid), float2 stores ----
    #pragma unroll
    for (int ni = 0; ni < 8; ni++) {
        const int gc = bnb * BN + wn + ni * 8 + lc * 2;
        const float b0 = bias[gc], b1 = bias[gc + 1];
        #pragma unroll
        for (int mi = 0; mi < 4; mi++) {
            const size_t gr = (size_t)bmb * BM + wm + mi * 16 + lr;
            float v0 = acc[mi][ni][0] + b0;
            float v1 = acc[mi][ni][1] + b1;
            float v2 = acc[mi][ni][2] + b0;
            float v3 = acc[mi][ni][3] + b1;
            if (act) {
                v0 = 1.0f / (1.0f + __expf(-v0));
                v1 = 1.0f / (1.0f + __expf(-v1));
                v2 = 1.0f / (1.0f + __expf(-v2));
                v3 = 1.0f / (1.0f + __expf(-v3));
            }
            *reinterpret_cast<float2*>(C + gr * Dd + gc)       = make_float2(v0, v1);
            *reinterpret_cast<float2*>(C + (gr + 8) * Dd + gc) = make_float2(v2, v3);
        }
    }
    #undef LOAD_STAGE
}

// ---------------------------------------------------------------------------
// Chunked linear-recurrence scan: h_t = g_t*h_{t-1} + (1-g_t)*u_t
// ---------------------------------------------------------------------------
__global__ void scan_phase1()
{
    const int d = blockIdx.x * blockDim.x + threadIdx.x;
    const int c = blockIdx.y;
    const int b = blockIdx.z;
    const size_t base = ((size_t)b * Tt + (size_t)c * CL) * Dd + d;

    float P = 1.0f, S = 0.0f;
    #pragma unroll 4
    for (int t = 0; t < CL; ++t) {
        const float gg = sc_g[base + (size_t)t * Dd];
        const float uu = sc_u[base + (size_t)t * Dd];
        S = fmaf(gg, S, (1.0f - gg) * uu);
        P *= gg;
    }
    const int idx = (b * NC + c) * Dd + d;
    sc_P[idx] = P;
    sc_S[idx] = S;
}

__global__ void scan_phase2()
{
    const int idx = blockIdx.x * blockDim.x + threadIdx.x;
    const int b = idx >> 10;
    const int d = idx & 1023;

    float carry = 0.0f;
    #pragma unroll
    for (int c = 0; c < NC; ++c) {
        const int k = (b * NC + c) * Dd + d;
        sc_C[k] = carry;
        carry = fmaf(sc_P[k], carry, sc_S[k]);
    }
}

__global__ void scan_phase3()
{
    const int d = blockIdx.x * blockDim.x + threadIdx.x;
    const int c = blockIdx.y;
    const int b = blockIdx.z;
    const size_t base = ((size_t)b * Tt + (size_t)c * CL) * Dd + d;

    float h = sc_C[(b * NC + c) * Dd + d];
    #pragma unroll 4
    for (int t = 0; t < CL; ++t) {
        const float gg = sc_g[base + (size_t)t * Dd];
        const float uu = sc_u[base + (size_t)t * Dd];
        h = fmaf(gg, h, (1.0f - gg) * uu);
        sc_h[base + (size_t)t * Dd] = h;
    }
}

// ---------------------------------------------------------------------------
extern "C" void kernel_launch(void* const* d_in, const int* in_sizes, int n_in,
                              void* d_out, int out_size)
{
    (void)in_sizes; (void)n_in; (void)out_size;

    const float* x  = (const float*)d_in[0];
    const float* Wi = (const float*)d_in[1];
    const float* bi = (const float*)d_in[2];
    const float* Wg = (const float*)d_in[3];
    const float* bg = (const float*)d_in[4];
    const float* Wo = (const float*)d_in[5];
    const float* bo = (const float*)d_in[6];
    float* out = (float*)d_out;

    float *u, *g, *h;
    cudaGetSymbolAddress((void**)&u, sc_u);
    cudaGetSymbolAddress((void**)&g, sc_g);
    cudaGetSymbolAddress((void**)&h, sc_h);

    cudaFuncSetAttribute(gemm_tc, cudaFuncAttributeMaxDynamicSharedMemorySize, SMEM_BYTES);

    const dim3 ggrid(Dd / BN, Mtot / BM);   // (8, 128)
    const dim3 gblk(256);

    gemm_tc<<<ggrid, gblk, SMEM_BYTES>>>(x, Wi, bi, u, 0);
    gemm_tc<<<ggrid, gblk, SMEM_BYTES>>>(x, Wg, bg, g, 1);

    const dim3 s_grid(Dd / 256, NC, Bb);    // (4, 32, 8)
    scan_phase1<<<s_grid, 256>>>();
    scan_phase2<<<32, 256>>>();
    scan_phase3<<<s_grid, 256>>>();

    gemm_tc<<<ggrid, gblk, SMEM_BYTES>>>(h, Wo, bo, out, 0);
}